// round 3
// baseline (speedup 1.0000x reference)
#include <cuda_runtime.h>
#include <math.h>
#include <stddef.h>
#include <stdint.h>

// ---------------------------------------------------------------------------
// GatedDeltaNet  B=2 S=2048 H=2048  HK=16 HV=32 DK=DV=128  conv K=4
// R3: recurrence re-tiled (8-lane reductions) + packed f32x2 FMA;
//     dedicated BN=64 SGEMM for the ba projection.
// ---------------------------------------------------------------------------
namespace {
constexpr int Bc = 2, Sc = 2048, Hc = 2048;
constexpr int DK = 128, DV = 128, HK = 16, HV = 32, Gc = 2;
constexpr int FQ  = 2*HK*DK + 2*HV*DV;   // 12288
constexpr int FBA = 2*HV;                // 64
constexpr int ROWH = 2*DK + 2*Gc*DV;     // 768
constexpr int BS = Bc*Sc;                // 4096
constexpr float EPS = 1e-6f;
constexpr float QSCALE = 0.08838834764831845f;  // DK^-0.5
}

// ------------------------- scratch (static device mem) ---------------------
__device__ float g_qkvz[(size_t)BS*FQ];
__device__ float g_ba  [(size_t)BS*FBA];
__device__ float g_q   [(size_t)BS*HK*DK];
__device__ float g_k   [(size_t)BS*HK*DK];
__device__ float g_v   [(size_t)BS*HV*DV];
__device__ float g_g   [(size_t)BS*HV];
__device__ float g_b   [(size_t)BS*HV];
__device__ float g_o   [(size_t)BS*HV*DV];

// ------------------------- f32x2 packed helpers (Blackwell) ----------------
using u64 = unsigned long long;
__device__ __forceinline__ u64 pk2(float lo, float hi) {
    u64 r; asm("mov.b64 %0, {%1, %2};" : "=l"(r) : "f"(lo), "f"(hi)); return r;
}
__device__ __forceinline__ void upk2(u64 v, float& lo, float& hi) {
    asm("mov.b64 {%0, %1}, %2;" : "=f"(lo), "=f"(hi) : "l"(v));
}
__device__ __forceinline__ u64 fma2(u64 a, u64 b, u64 c) {
    u64 d; asm("fma.rn.f32x2 %0, %1, %2, %3;" : "=l"(d) : "l"(a), "l"(b), "l"(c));
    return d;
}
__device__ __forceinline__ u64 mul2(u64 a, u64 b) {
    u64 d; asm("mul.rn.f32x2 %0, %1, %2;" : "=l"(d) : "l"(a), "l"(b)); return d;
}

// ======================= TF32 tensor-core GEMM ==============================
namespace tfg {
constexpr int BM = 128, BN = 128, BK = 32;
constexpr int APAD = 36;
constexpr int BPAD = 136;
constexpr int ASZ = BM * APAD;
constexpr int BSZ = BK * BPAD;
constexpr int SMEM_FLOATS = 2 * (ASZ + BSZ);     // 71680 B
}

__device__ __forceinline__ uint32_t f2tf32(float x) {
    uint32_t r;
    asm("cvt.rna.tf32.f32 %0, %1;" : "=r"(r) : "f"(x));
    return r;
}
__device__ __forceinline__ void cp16(void* sdst, const void* gsrc) {
    uint32_t s = (uint32_t)__cvta_generic_to_shared(sdst);
    asm volatile("cp.async.cg.shared.global [%0], [%1], 16;" :: "r"(s), "l"(gsrc));
}
__device__ __forceinline__ void cp_commit() {
    asm volatile("cp.async.commit_group;");
}
template<int N>
__device__ __forceinline__ void cp_wait() {
    asm volatile("cp.async.wait_group %0;" :: "n"(N));
}
__device__ __forceinline__ void mma_tf32(float* d, const uint32_t* a, const uint32_t* b) {
    asm volatile(
        "mma.sync.aligned.m16n8k8.row.col.f32.tf32.tf32.f32 "
        "{%0,%1,%2,%3},{%4,%5,%6,%7},{%8,%9},{%0,%1,%2,%3};"
        : "+f"(d[0]), "+f"(d[1]), "+f"(d[2]), "+f"(d[3])
        : "r"(a[0]), "r"(a[1]), "r"(a[2]), "r"(a[3]), "r"(b[0]), "r"(b[1]));
}

__global__ __launch_bounds__(256, 2) void gemm_tf32(const float* __restrict__ A,
                                                    const float* __restrict__ B,
                                                    float* __restrict__ C,
                                                    int M, int N, int K) {
    using namespace tfg;
    extern __shared__ float sm[];
    float* As[2] = { sm,         sm + ASZ };
    float* Bs[2] = { sm + 2*ASZ, sm + 2*ASZ + BSZ };

    const int tid  = threadIdx.x;
    const int lane = tid & 31;
    const int wid  = tid >> 5;
    const int mw = (wid >> 2) * 64;
    const int nw = (wid & 3) * 32;
    const int r = lane >> 2;
    const int c = lane & 3;
    const int bm = blockIdx.y * BM;
    const int bn = blockIdx.x * BN;

    float acc[4][4][4];
#pragma unroll
    for (int i = 0; i < 4; i++)
#pragma unroll
        for (int j = 0; j < 4; j++)
#pragma unroll
            for (int e = 0; e < 4; e++) acc[i][j][e] = 0.f;

    const int ntiles = K / BK;

    auto issue_tile = [&](int t, int st) {
#pragma unroll
        for (int i = 0; i < 4; i++) {
            int idx = tid + 256 * i;
            int row = idx >> 3, c4 = (idx & 7) << 2;
            cp16(As[st] + row * APAD + c4,
                 A + (size_t)(bm + row) * K + t * BK + c4);
        }
#pragma unroll
        for (int i = 0; i < 4; i++) {
            int idx = tid + 256 * i;
            int row = idx >> 5, c4 = (idx & 31) << 2;
            cp16(Bs[st] + row * BPAD + c4,
                 B + (size_t)(t * BK + row) * N + bn + c4);
        }
        cp_commit();
    };

    issue_tile(0, 0);

    for (int t = 0; t < ntiles; t++) {
        const int st = t & 1;
        if (t + 1 < ntiles) {
            issue_tile(t + 1, st ^ 1);
            cp_wait<1>();
        } else {
            cp_wait<0>();
        }
        __syncthreads();

        const float* Ab = As[st];
        const float* Bb = Bs[st];
#pragma unroll
        for (int kk = 0; kk < 4; kk++) {
            const int k0 = kk * 8;
            uint32_t af[4][4];
#pragma unroll
            for (int i = 0; i < 4; i++) {
                const float* p = Ab + (mw + 16*i + r) * APAD + k0 + c;
                af[i][0] = f2tf32(p[0]);
                af[i][1] = f2tf32(p[8 * APAD]);
                af[i][2] = f2tf32(p[4]);
                af[i][3] = f2tf32(p[8 * APAD + 4]);
            }
            uint32_t bf[4][2];
#pragma unroll
            for (int j = 0; j < 4; j++) {
                const float* p = Bb + (k0 + c) * BPAD + nw + 8*j + r;
                bf[j][0] = f2tf32(p[0]);
                bf[j][1] = f2tf32(p[4 * BPAD]);
            }
#pragma unroll
            for (int i = 0; i < 4; i++)
#pragma unroll
                for (int j = 0; j < 4; j++)
                    mma_tf32(acc[i][j], af[i], bf[j]);
        }
        __syncthreads();
    }

#pragma unroll
    for (int i = 0; i < 4; i++) {
#pragma unroll
        for (int j = 0; j < 4; j++) {
            int row = bm + mw + 16*i + r;
            int col = bn + nw + 8*j + 2*c;
            *(float2*)&C[(size_t)row * N + col] =
                make_float2(acc[i][j][0], acc[i][j][1]);
            *(float2*)&C[(size_t)(row + 8) * N + col] =
                make_float2(acc[i][j][2], acc[i][j][3]);
        }
    }
}

// ------------------- skinny fp32 SGEMM for ba: tile 128x64x8 ---------------
__global__ __launch_bounds__(256) void sgemm_ba(const float* __restrict__ A,
                                                const float* __restrict__ B,
                                                float* __restrict__ C,
                                                int M, int N, int K) {
    __shared__ float As[8][128];
    __shared__ float Bs[8][64];
    const int tid = threadIdx.x;
    const int bm = blockIdx.y * 128;
    const int tr = (tid >> 4) * 8;          // 16 groups x 8 rows
    const int tc = (tid & 15) * 4;          // 16 groups x 4 cols
    const int aRow = tid >> 1, aCol = (tid & 1) * 4;
    const int bRow = tid >> 4, bCol = (tid & 15) * 4;   // tid<128 loads B
    const float* Ag = A + (size_t)(bm + aRow) * K + aCol;
    float acc[8][4];
#pragma unroll
    for (int i = 0; i < 8; i++)
#pragma unroll
        for (int j = 0; j < 4; j++) acc[i][j] = 0.f;

    for (int k0 = 0; k0 < K; k0 += 8) {
        float4 av = *(const float4*)(Ag + k0);
        As[aCol+0][aRow] = av.x; As[aCol+1][aRow] = av.y;
        As[aCol+2][aRow] = av.z; As[aCol+3][aRow] = av.w;
        if (tid < 128)
            *(float4*)&Bs[bRow][bCol] =
                *(const float4*)(B + (size_t)(k0 + bRow) * N + bCol);
        __syncthreads();
#pragma unroll
        for (int kk = 0; kk < 8; kk++) {
            float4 a0 = *(const float4*)&As[kk][tr];
            float4 a1 = *(const float4*)&As[kk][tr+4];
            float4 bv = *(const float4*)&Bs[kk][tc];
            float a[8]  = {a0.x,a0.y,a0.z,a0.w,a1.x,a1.y,a1.z,a1.w};
            float bb[4] = {bv.x,bv.y,bv.z,bv.w};
#pragma unroll
            for (int i = 0; i < 8; i++)
#pragma unroll
                for (int j = 0; j < 4; j++) acc[i][j] = fmaf(a[i], bb[j], acc[i][j]);
        }
        __syncthreads();
    }
#pragma unroll
    for (int i = 0; i < 8; i++)
        *(float4*)&C[(size_t)(bm + tr + i) * N + tc] =
            make_float4(acc[i][0], acc[i][1], acc[i][2], acc[i][3]);
}

// ------------- conv(K=4)+silu+l2norm for q,k (one block per b,s,hk) --------
__global__ __launch_bounds__(128) void conv_qk_kernel(const float* __restrict__ qkvz,
        const float* __restrict__ cw, const float* __restrict__ cb,
        float* __restrict__ qo, float* __restrict__ ko) {
    int bsh = blockIdx.x;
    int hk = bsh % HK;
    int bs = bsh / HK;
    int s = bs % Sc;
    int d = threadIdx.x;
    int cq = hk*DK + d;
    int ck = HK*DK + cq;
    const float* base = qkvz + (size_t)bs*FQ + hk*ROWH + d;
    float aq = cb[cq], ak = cb[ck];
#pragma unroll
    for (int j = 0; j < 4; j++) {
        int t = s - 3 + j;
        if (t >= 0) {
            const float* rp = base + (ptrdiff_t)(j - 3) * FQ;
            aq = fmaf(cw[cq*4+j], rp[0],  aq);
            ak = fmaf(cw[ck*4+j], rp[DK], ak);
        }
    }
    aq = aq / (1.f + expf(-aq));
    ak = ak / (1.f + expf(-ak));
    float sq = aq*aq, sk = ak*ak;
#pragma unroll
    for (int off = 16; off; off >>= 1) {
        sq += __shfl_xor_sync(0xffffffffu, sq, off);
        sk += __shfl_xor_sync(0xffffffffu, sk, off);
    }
    __shared__ float red[8];
    int w = d >> 5, lane = d & 31;
    if (lane == 0) { red[w] = sq; red[4+w] = sk; }
    __syncthreads();
    float tq = red[0]+red[1]+red[2]+red[3];
    float tk = red[4]+red[5]+red[6]+red[7];
    size_t oi = (size_t)bs*HK*DK + hk*DK + d;
    qo[oi] = aq * rsqrtf(tq + EPS) * QSCALE;
    ko[oi] = ak * rsqrtf(tk + EPS);
}

// ------------- conv(K=4)+silu for v (elementwise) ---------------------------
__global__ __launch_bounds__(256) void conv_v_kernel(const float* __restrict__ qkvz,
        const float* __restrict__ cw, const float* __restrict__ cb,
        float* __restrict__ vo) {
    size_t idx = (size_t)blockIdx.x * 256 + threadIdx.x;
    int d  = (int)(idx % DV);
    int hv = (int)((idx / DV) % HV);
    ptrdiff_t bs = (ptrdiff_t)(idx / ((size_t)DV*HV));
    int s = (int)(bs % Sc);
    int ccol = 2*HK*DK + hv*DV + d;
    int hk = hv / Gc, gi = hv % Gc;
    int col = hk*ROWH + 2*DK + gi*DV + d;
    float acc = cb[ccol];
#pragma unroll
    for (int j = 0; j < 4; j++) {
        int t = s - 3 + j;
        if (t >= 0)
            acc = fmaf(cw[ccol*4+j], qkvz[(size_t)(bs + j - 3)*FQ + col], acc);
    }
    vo[idx] = acc / (1.f + expf(-acc));
}

// ------------- g = -exp(a_log)*softplus(a+dt), beta = sigmoid(b) ------------
__global__ __launch_bounds__(256) void gb_kernel(const float* __restrict__ ba,
        const float* __restrict__ a_log, const float* __restrict__ dt_bias,
        float* __restrict__ gg, float* __restrict__ bb) {
    int idx = blockIdx.x * 256 + threadIdx.x;
    if (idx >= BS*HV) return;
    int hv = idx % HV;
    int bs = idx / HV;
    int hk = hv / Gc, gi = hv % Gc;
    float bval = ba[(size_t)bs*FBA + hk*2*Gc + gi];
    float aval = ba[(size_t)bs*FBA + hk*2*Gc + Gc + gi];
    float xin = aval + dt_bias[hv];
    float sp = (xin > 20.f) ? xin : log1pf(expf(xin));
    gg[idx] = -expf(a_log[hv]) * sp;
    bb[idx] = 1.f / (1.f + expf(-bval));
}

// ------------- delta-rule recurrence (R3 layout) -----------------------------
// One CTA per (b,hv,v-slice of 64). 256 threads = 8 warps; warp w owns v-cols
// [w*8, w*8+8). Lane = (kg = lane&7, vg = lane>>3): thread owns k-rows
// [kg*16, kg*16+16) and 2 v-cols (vw + vg*2 + {0,1}) packed in f32x2.
// Reductions over the 8 kg lanes (shfl.xor 1,2,4).
constexpr int TCH = 32;
__global__ __launch_bounds__(256) void recur_kernel(const float* __restrict__ q,
        const float* __restrict__ k, const float* __restrict__ v,
        const float* __restrict__ g, const float* __restrict__ be,
        float* __restrict__ o) {
    int bid = blockIdx.x;
    int slice = bid & 1;
    int hv = (bid >> 1) & (HV - 1);
    int b  = bid >> 6;
    int hk = hv >> 1;
    int vs0 = slice * 64;
    __shared__ float sq[TCH][128];
    __shared__ float sk[TCH][128];
    __shared__ float sv[TCH][64];
    __shared__ float sg[TCH], sb[TCH];
    const int tid = threadIdx.x, lane = tid & 31, w = tid >> 5;
    const int kg = lane & 7;          // k-group (reduction dim)
    const int vg = lane >> 3;         // v-group
    const int vc = w * 8 + vg * 2;    // first of this thread's 2 v-cols
    const float* qb = q + ((size_t)b*Sc*HK + hk) * DK;
    const float* kb = k + ((size_t)b*Sc*HK + hk) * DK;
    const float* vb = v + ((size_t)b*Sc*HV + hv) * DV + vs0;
    const float* gp = g + (size_t)b*Sc*HV + hv;
    const float* bp = be + (size_t)b*Sc*HV + hv;
    float* ob = o + ((size_t)b*Sc*HV + hv) * DV + vs0;

    const u64 Z2 = pk2(0.f, 0.f);
    const u64 NEG1 = pk2(-1.f, -1.f);

    u64 St[16];                        // 16 k-rows x 2 v-cols
#pragma unroll
    for (int rr = 0; rr < 16; rr++) St[rr] = Z2;

    for (int s0 = 0; s0 < Sc; s0 += TCH) {
        __syncthreads();
        for (int i = tid; i < TCH*32; i += 256) {
            int t = i >> 5, c4 = (i & 31) * 4;
            *(float4*)&sq[t][c4] = *(const float4*)&qb[(size_t)(s0+t)*HK*DK + c4];
            *(float4*)&sk[t][c4] = *(const float4*)&kb[(size_t)(s0+t)*HK*DK + c4];
        }
        for (int i = tid; i < TCH*16; i += 256) {
            int t = i >> 4, c4 = (i & 15) * 4;
            *(float4*)&sv[t][c4] = *(const float4*)&vb[(size_t)(s0+t)*HV*DV + c4];
        }
        if (tid < TCH) {
            sg[tid] = expf(gp[(size_t)(s0+tid)*HV]);   // pre-exponentiate
            sb[tid] = bp[(size_t)(s0+tid)*HV];
        }
        __syncthreads();

        for (int t = 0; t < TCH; t++) {
            float dec = sg[t];
            float bt  = sb[t];
            u64 dec2 = pk2(dec, dec);
            u64 bt2  = pk2(bt, bt);
            float kr[16], qr[16];
#pragma unroll
            for (int i = 0; i < 4; i++) {
                float4 kv4 = *(const float4*)&sk[t][kg*16 + 4*i];
                float4 qv4 = *(const float4*)&sq[t][kg*16 + 4*i];
                kr[4*i+0]=kv4.x; kr[4*i+1]=kv4.y; kr[4*i+2]=kv4.z; kr[4*i+3]=kv4.w;
                qr[4*i+0]=qv4.x; qr[4*i+1]=qv4.y; qr[4*i+2]=qv4.z; qr[4*i+3]=qv4.w;
            }
            // phase 1: decay + kS = k . S  (packed over 2 v-cols)
            u64 acc2 = Z2;
#pragma unroll
            for (int rr = 0; rr < 16; rr++) {
                u64 k2 = pk2(kr[rr], kr[rr]);
                St[rr] = mul2(St[rr], dec2);
                acc2 = fma2(k2, St[rr], acc2);
            }
            float alo, ahi;
            upk2(acc2, alo, ahi);
#pragma unroll
            for (int off = 1; off < 8; off <<= 1) {
                alo += __shfl_xor_sync(0xffffffffu, alo, off);
                ahi += __shfl_xor_sync(0xffffffffu, ahi, off);
            }
            u64 kS2 = pk2(alo, ahi);
            // dv = bt * (v - kS)
            float2 vv = *(const float2*)&sv[t][vc];
            u64 v2 = pk2(vv.x, vv.y);
            u64 dv2 = mul2(fma2(kS2, NEG1, v2), bt2);
            // phase 2: S += k (x) dv ; o = q . S
            u64 o2 = Z2;
#pragma unroll
            for (int rr = 0; rr < 16; rr++) {
                u64 k2 = pk2(kr[rr], kr[rr]);
                u64 q2 = pk2(qr[rr], qr[rr]);
                St[rr] = fma2(k2, dv2, St[rr]);
                o2 = fma2(q2, St[rr], o2);
            }
            float olo, ohi;
            upk2(o2, olo, ohi);
#pragma unroll
            for (int off = 1; off < 8; off <<= 1) {
                olo += __shfl_xor_sync(0xffffffffu, olo, off);
                ohi += __shfl_xor_sync(0xffffffffu, ohi, off);
            }
            if (kg == 0)
                *(float2*)&ob[(size_t)(s0+t)*HV*DV + vc] = make_float2(olo, ohi);
        }
    }
}

// ------------- y = o*silu(z); RMSNorm over DV (in place into o) -------------
__global__ __launch_bounds__(128) void ynorm_kernel(const float* __restrict__ qkvz,
        const float* __restrict__ nw, float* __restrict__ o) {
    int bsh = blockIdx.x;
    int hv = bsh & (HV - 1);
    int bs = bsh >> 5;
    int d = threadIdx.x;
    int hk = hv >> 1, gi = hv & 1;
    float z = qkvz[(size_t)bs*FQ + hk*ROWH + 2*DK + Gc*DV + gi*DV + d];
    size_t oi = (size_t)bsh*DV + d;
    float y = o[oi] * (z / (1.f + expf(-z)));
    float ss = y*y;
#pragma unroll
    for (int off = 16; off; off >>= 1) ss += __shfl_xor_sync(0xffffffffu, ss, off);
    __shared__ float red[4];
    int wdx = d >> 5, lane = d & 31;
    if (lane == 0) red[wdx] = ss;
    __syncthreads();
    float var = (red[0]+red[1]+red[2]+red[3]) * (1.f/DV);
    o[oi] = y * rsqrtf(var + EPS) * nw[d];
}

// ---------------------------------------------------------------------------
extern "C" void kernel_launch(void* const* d_in, const int* in_sizes, int n_in,
                              void* d_out, int out_size) {
    const float* x       = (const float*)d_in[0];
    const float* w_qkvz  = (const float*)d_in[1];
    const float* w_ba    = (const float*)d_in[2];
    const float* conv_w  = (const float*)d_in[3];
    const float* conv_b  = (const float*)d_in[4];
    const float* a_log   = (const float*)d_in[5];
    const float* dt_bias = (const float*)d_in[6];
    const float* norm_w  = (const float*)d_in[7];
    const float* w_o     = (const float*)d_in[8];
    float* out = (float*)d_out;

    float *qkvz, *ba, *q, *k, *v, *gg, *bb, *o;
    cudaGetSymbolAddress((void**)&qkvz, g_qkvz);
    cudaGetSymbolAddress((void**)&ba,   g_ba);
    cudaGetSymbolAddress((void**)&q,    g_q);
    cudaGetSymbolAddress((void**)&k,    g_k);
    cudaGetSymbolAddress((void**)&v,    g_v);
    cudaGetSymbolAddress((void**)&gg,   g_g);
    cudaGetSymbolAddress((void**)&bb,   g_b);
    cudaGetSymbolAddress((void**)&o,    g_o);

    const int smem_bytes = tfg::SMEM_FLOATS * sizeof(float);
    cudaFuncSetAttribute(gemm_tf32, cudaFuncAttributeMaxDynamicSharedMemorySize,
                         smem_bytes);

    // 1) big input projection (TF32 TC) + skinny ba projection (fp32)
    gemm_tf32<<<dim3(FQ/128, BS/128), 256, smem_bytes>>>(x, w_qkvz, qkvz, BS, FQ, Hc);
    sgemm_ba<<<dim3(1, BS/128), 256>>>(x, w_ba, ba, BS, FBA, Hc);

    // 2) conv + silu (+ l2norm for q,k), gate params
    conv_qk_kernel<<<BS*HK, 128>>>(qkvz, conv_w, conv_b, q, k);
    conv_v_kernel<<<(BS*HV*DV)/256, 256>>>(qkvz, conv_w, conv_b, v);
    gb_kernel<<<(BS*HV + 255)/256, 256>>>(ba, a_log, dt_bias, gg, bb);

    // 3) sequential delta-rule scan
    recur_kernel<<<Bc*HV*2, 256>>>(q, k, v, gg, bb, o);

    // 4) gate + RMSNorm, then output projection (TF32 TC)
    ynorm_kernel<<<BS*HV, 128>>>(qkvz, norm_w, o);
    gemm_tf32<<<dim3(Hc/128, BS/128), 256, smem_bytes>>>(o, w_o, out, BS, Hc, HV*DV);
}